// round 1
// baseline (speedup 1.0000x reference)
#include <cuda_runtime.h>
#include <cuda_bf16.h>
#include <math.h>

// ---------------- problem constants ----------------
#define BB   128
#define TT   64
#define NIMG (BB*TT)          // 8192
#define HI   50
#define WI   60
#define HO   25
#define WO   30
#define EMB  750
#define QS   100
#define HSZ  400
#define NCLS 10

// ---------------- f32x2 packed helpers ----------------
typedef unsigned long long f32x2;

__device__ __forceinline__ f32x2 pk2(float x, float y) {
    f32x2 r; asm("mov.b64 %0, {%1, %2};" : "=l"(r) : "f"(x), "f"(y)); return r;
}
__device__ __forceinline__ void unpk2(f32x2 v, float &x, float &y) {
    asm("mov.b64 {%0, %1}, %2;" : "=f"(x), "=f"(y) : "l"(v));
}
__device__ __forceinline__ void fma2(f32x2 &d, f32x2 a, f32x2 b) {
    asm("fma.rn.f32x2 %0, %1, %2, %0;" : "+l"(d) : "l"(a), "l"(b));
}
__device__ __forceinline__ f32x2 add2(f32x2 a, f32x2 b) {
    f32x2 d; asm("add.rn.f32x2 %0, %1, %2;" : "=l"(d) : "l"(a), "l"(b)); return d;
}
__device__ __forceinline__ float lky(float x) { return x >= 0.f ? x : 0.01f * x; }

// ---------------- scratch (static device memory; allowed) ----------------
__device__ float g_emb[NIMG * EMB];      // 24.6 MB
__device__ float g_E[NIMG * QS];         //  3.3 MB  (emb @ Qw[:750] + Qb)
__device__ float g_Hall[NIMG * HSZ];     // 13.1 MB
__device__ float g_OutAll[NIMG * QS];    //  3.3 MB

// =====================================================================
// Kernel A: fused conv1(1->16,3x3,s1,p1)+leaky -> conv2(16->1,3x3,s2,p1)+leaky
// One CTA per image. Rolling 4-row ring buffer of conv1 output in SMEM.
// Channel pairs packed as f32x2.
// =====================================================================
__global__ void __launch_bounds__(256) conv_embed_kernel(
    const float *__restrict__ In,
    const float *__restrict__ w1, const float *__restrict__ b1,
    const float *__restrict__ w2, const float *__restrict__ b2,
    float *__restrict__ emb_out)
{
    __shared__ float img[HI * WI];            // 12 KB
    __shared__ f32x2 rb[4][WI][8];            // ring buffer: [row&3][x][cpair]
    __shared__ f32x2 sw1[9][8];               // conv1 weights, pair-packed over channels
    __shared__ f32x2 sw2[9][8];               // conv2 weights, pair-packed over channels
    __shared__ f32x2 sb1[8];
    __shared__ float c2part[30][8];
    __shared__ float emb_s[EMB];

    const int tid = threadIdx.x;
    const float *imgg = In + (size_t)blockIdx.x * (HI * WI);

    for (int i = tid; i < HI * WI; i += 256) img[i] = imgg[i];
    if (tid < 72) {
        int tap = tid / 8, cp = tid % 8;
        sw1[tap][cp] = pk2(w1[(2 * cp) * 9 + tap], w1[(2 * cp + 1) * 9 + tap]);
        sw2[tap][cp] = pk2(w2[(2 * cp) * 9 + tap], w2[(2 * cp + 1) * 9 + tap]);
    }
    if (tid < 8) sb1[tid] = pk2(b1[2 * tid], b1[2 * tid + 1]);
    // zero ring slot 3 (serves as conv1 row -1 at i2 == 0)
    for (int i = tid; i < WI * 8; i += 256) rb[3][i / 8][i % 8] = 0ull;
    const float bias2 = b2[0];
    __syncthreads();

    for (int i2 = 0; i2 < HO; i2++) {
        // ---- conv1: compute rows r0 = 2*i2 and r0+1 ----
        // tasks: (row_sel 0..1, xg 0..14, cp 0..7) -> 240; each does 4 x-outputs
        if (tid < 240) {
            int row_sel = tid / 120;
            int v = tid % 120;
            int xg = v / 8;
            int cp = v % 8;
            int r  = 2 * i2 + row_sel;
            int xb = xg * 4;
            f32x2 a0 = sb1[cp], a1 = a0, a2 = a0, a3 = a0;
            #pragma unroll
            for (int dy = 0; dy < 3; dy++) {
                int ry = r + dy - 1;
                float c[6];
                #pragma unroll
                for (int d = 0; d < 6; d++) {
                    int cx = xb - 1 + d;
                    c[d] = (ry >= 0 && ry < HI && cx >= 0 && cx < WI) ? img[ry * WI + cx] : 0.f;
                }
                #pragma unroll
                for (int dx = 0; dx < 3; dx++) {
                    f32x2 w = sw1[dy * 3 + dx][cp];
                    fma2(a0, pk2(c[dx + 0], c[dx + 0]), w);
                    fma2(a1, pk2(c[dx + 1], c[dx + 1]), w);
                    fma2(a2, pk2(c[dx + 2], c[dx + 2]), w);
                    fma2(a3, pk2(c[dx + 3], c[dx + 3]), w);
                }
            }
            int rs = r & 3;
            float lo, hi;
            unpk2(a0, lo, hi); rb[rs][xb + 0][cp] = pk2(lky(lo), lky(hi));
            unpk2(a1, lo, hi); rb[rs][xb + 1][cp] = pk2(lky(lo), lky(hi));
            unpk2(a2, lo, hi); rb[rs][xb + 2][cp] = pk2(lky(lo), lky(hi));
            unpk2(a3, lo, hi); rb[rs][xb + 3][cp] = pk2(lky(lo), lky(hi));
        }
        __syncthreads();
        // ---- conv2 partials: tasks (x2 0..29, cp 0..7) ----
        if (tid < 240) {
            int x2 = tid / 8, cp = tid % 8;
            f32x2 acc = 0ull;
            #pragma unroll
            for (int dy = 0; dy < 3; dy++) {
                int rr = (2 * i2 + dy - 1) & 3;
                #pragma unroll
                for (int dx = 0; dx < 3; dx++) {
                    int cx = 2 * x2 + dx - 1;
                    if (cx >= 0 && cx < WI)
                        fma2(acc, rb[rr][cx][cp], sw2[dy * 3 + dx][cp]);
                }
            }
            float lo, hi; unpk2(acc, lo, hi);
            c2part[x2][cp] = lo + hi;
        }
        __syncthreads();
        if (tid < 30) {
            float s = bias2;
            #pragma unroll
            for (int cp = 0; cp < 8; cp++) s += c2part[tid][cp];
            emb_s[i2 * 30 + tid] = lky(s);
        }
        // reduce finishes before the sync inside the next iteration -> safe
    }
    __syncthreads();
    float *eo = emb_out + (size_t)blockIdx.x * EMB;
    for (int i = tid; i < EMB; i += 256) eo[i] = emb_s[i];
}

// =====================================================================
// GEMM: C[M x 100] = A[M x K] @ W[K x 100] + bias, optional tanh.
// CTA tile 64 x 100; 200 active threads, each 8 rows x 4 cols (f32x2 col pairs).
// =====================================================================
template <bool TANH>
__global__ void __launch_bounds__(256) gemm100_kernel(
    const float *__restrict__ A, const float *__restrict__ W,
    const float *__restrict__ bias, float *__restrict__ C, int M, int K)
{
    __shared__ __align__(16) float As[32][65];   // [kk][m]
    __shared__ __align__(16) float Ws[32][104];  // [kk][j]

    const int tid = threadIdx.x;
    const int row0 = blockIdx.x * 64;
    const int tx = tid % 25;   // col group: cols 4*tx .. 4*tx+3
    const int ty = tid / 25;   // row group: rows 8*ty .. 8*ty+7
    const bool act = (tid < 200);

    f32x2 acc[8][2];
    #pragma unroll
    for (int r = 0; r < 8; r++) { acc[r][0] = 0ull; acc[r][1] = 0ull; }

    for (int k0 = 0; k0 < K; k0 += 32) {
        for (int e = tid; e < 64 * 32; e += 256) {
            int m = e >> 5, kk = e & 31;
            int k = k0 + kk;
            As[kk][m] = (k < K) ? A[(size_t)(row0 + m) * K + k] : 0.f;
        }
        for (int e = tid; e < 32 * 100; e += 256) {
            int kk = e / 100, j = e % 100;
            int k = k0 + kk;
            Ws[kk][j] = (k < K) ? W[(size_t)k * 100 + j] : 0.f;
        }
        __syncthreads();
        if (act) {
            #pragma unroll
            for (int kk = 0; kk < 32; kk++) {
                f32x2 w0 = *(const f32x2 *)&Ws[kk][4 * tx];
                f32x2 w1 = *(const f32x2 *)&Ws[kk][4 * tx + 2];
                #pragma unroll
                for (int r = 0; r < 8; r++) {
                    float a = As[kk][8 * ty + r];
                    f32x2 aa = pk2(a, a);
                    fma2(acc[r][0], aa, w0);
                    fma2(acc[r][1], aa, w1);
                }
            }
        }
        __syncthreads();
    }
    if (act) {
        float b0 = bias[4 * tx + 0], b1_ = bias[4 * tx + 1];
        float b2_ = bias[4 * tx + 2], b3 = bias[4 * tx + 3];
        #pragma unroll
        for (int r = 0; r < 8; r++) {
            float x0, x1, x2, x3;
            unpk2(acc[r][0], x0, x1);
            unpk2(acc[r][1], x2, x3);
            x0 += b0; x1 += b1_; x2 += b2_; x3 += b3;
            if (TANH) { x0 = tanhf(x0); x1 = tanhf(x1); x2 = tanhf(x2); x3 = tanhf(x3); }
            float4 v = make_float4(x0, x1, x2, x3);
            *(float4 *)&C[(size_t)(row0 + 8 * ty + r) * 100 + 4 * tx] = v;
        }
    }
}

// =====================================================================
// Recurrence: one CTA per batch element, weights live in registers.
// Rt = tanh(H @ R_w + R_b); Qt = tanh(E_t + Rt @ Qw_r);
// H  = alpha*H + (1-alpha)*Qt ; store H to g_Hall.
// =====================================================================
__global__ void __launch_bounds__(512) recurrence_kernel(
    const float *__restrict__ Rw,   // 400 x 100
    const float *__restrict__ Rb,   // 100
    const float *__restrict__ Qw,   // 850 x 100 (rows 750.. are the Rt part)
    const float *__restrict__ E,    // [B*T][100], already includes Q_b
    float *__restrict__ Hall)       // [B*T][400]
{
    __shared__ __align__(16) float sH[HSZ];
    __shared__ float sRt[QS];
    __shared__ float sQt[QS];
    __shared__ __align__(16) float part[1008];   // part[s*100 + j]

    const int tid = threadIdx.x;
    const int b   = blockIdx.x;
    const int jp  = tid % 50;     // output pair: cols 2*jp, 2*jp+1
    const int ks  = tid / 50;     // k-slice
    const bool act = (tid < 500); // 10 slices x 50 pairs

    f32x2 w1r[40];  // R_w slice: k in [40*ks, 40*ks+40)
    f32x2 w2r[10];  // Qw_r slice: k in [10*ks, 10*ks+10)
    if (act) {
        #pragma unroll
        for (int kk = 0; kk < 40; kk++) {
            int k = ks * 40 + kk;
            w1r[kk] = *(const f32x2 *)&Rw[(size_t)k * 100 + 2 * jp];
        }
        #pragma unroll
        for (int kk = 0; kk < 10; kk++) {
            int k = ks * 10 + kk;
            w2r[kk] = *(const f32x2 *)&Qw[(size_t)(750 + k) * 100 + 2 * jp];
        }
    }
    for (int i = tid; i < HSZ; i += 512) sH[i] = 0.f;
    __syncthreads();

    const float *Eb = E + (size_t)b * TT * QS;
    float *Hb = Hall + (size_t)b * TT * HSZ;

    for (int t = 0; t < TT; t++) {
        // --- GEMV1: H(400) -> 100 ---
        if (act) {
            f32x2 a0 = 0ull, a1 = 0ull;
            #pragma unroll
            for (int kk = 0; kk < 40; kk += 2) {
                float h0 = sH[ks * 40 + kk];
                float h1 = sH[ks * 40 + kk + 1];
                fma2(a0, pk2(h0, h0), w1r[kk]);
                fma2(a1, pk2(h1, h1), w1r[kk + 1]);
            }
            *(f32x2 *)&part[ks * 100 + 2 * jp] = add2(a0, a1);
        }
        __syncthreads();
        if (tid < 100) {
            float s = Rb[tid];
            #pragma unroll
            for (int ss = 0; ss < 10; ss++) s += part[ss * 100 + tid];
            sRt[tid] = tanhf(s);
        }
        __syncthreads();
        // --- GEMV2: Rt(100) -> 100 ---
        if (act) {
            f32x2 a = 0ull;
            #pragma unroll
            for (int kk = 0; kk < 10; kk++) {
                float h = sRt[ks * 10 + kk];
                fma2(a, pk2(h, h), w2r[kk]);
            }
            *(f32x2 *)&part[ks * 100 + 2 * jp] = a;
        }
        __syncthreads();
        if (tid < 100) {
            float s = Eb[t * QS + tid];
            #pragma unroll
            for (int ss = 0; ss < 10; ss++) s += part[ss * 100 + tid];
            sQt[tid] = tanhf(s);
        }
        __syncthreads();
        // --- H update + store ---
        if (tid < HSZ) {
            const float alphas[4] = {0.0f, 0.25f, 0.5f, 0.95f};
            float al = alphas[tid / 100];
            float hn = al * sH[tid] + (1.f - al) * sQt[tid % 100];
            sH[tid] = hn;
            Hb[t * HSZ + tid] = hn;
        }
        __syncthreads();
    }
}

// =====================================================================
// Logits + softmax. One CTA per batch row.
// logits[b,c] = sum_{idx<6400} OutAll[b*6400+idx] * OutW[idx*10+c] + OutB[c]
// =====================================================================
__global__ void __launch_bounds__(256) logits_kernel(
    const float *__restrict__ OutAll, const float *__restrict__ OutW,
    const float *__restrict__ OutB, float *__restrict__ out)
{
    const int b = blockIdx.x, tid = threadIdx.x;
    const float *Ob = OutAll + (size_t)b * (TT * QS);

    float acc[NCLS];
    #pragma unroll
    for (int c = 0; c < NCLS; c++) acc[c] = 0.f;

    for (int i = tid; i < TT * QS; i += 256) {
        float v = Ob[i];
        const float *wr = OutW + (size_t)i * NCLS;
        #pragma unroll
        for (int c = 0; c < NCLS; c++) acc[c] += v * wr[c];
    }
    #pragma unroll
    for (int c = 0; c < NCLS; c++)
        #pragma unroll
        for (int o = 16; o > 0; o >>= 1)
            acc[c] += __shfl_down_sync(0xffffffffu, acc[c], o);

    __shared__ float wpart[8][NCLS];
    int w = tid >> 5, l = tid & 31;
    if (l == 0)
        #pragma unroll
        for (int c = 0; c < NCLS; c++) wpart[w][c] = acc[c];
    __syncthreads();

    __shared__ float slog[NCLS];
    if (tid < NCLS) {
        float s = OutB[tid];
        #pragma unroll
        for (int ww = 0; ww < 8; ww++) s += wpart[ww][tid];
        slog[tid] = s;
    }
    __syncthreads();
    __shared__ float smax, ssum;
    if (tid == 0) {
        float m = slog[0];
        #pragma unroll
        for (int c = 1; c < NCLS; c++) m = fmaxf(m, slog[c]);
        float su = 0.f;
        #pragma unroll
        for (int c = 0; c < NCLS; c++) su += expf(slog[c] - m);
        smax = m; ssum = su;
    }
    __syncthreads();
    if (tid < NCLS) out[(size_t)b * NCLS + tid] = expf(slog[tid] - smax) / ssum;
}

// =====================================================================
extern "C" void kernel_launch(void *const *d_in, const int *in_sizes, int n_in,
                              void *d_out, int out_size)
{
    const float *In     = (const float *)d_in[0];
    const float *conv1w = (const float *)d_in[1];
    const float *conv1b = (const float *)d_in[2];
    const float *conv2w = (const float *)d_in[3];
    const float *conv2b = (const float *)d_in[4];
    const float *Rw     = (const float *)d_in[5];
    const float *Rb     = (const float *)d_in[6];
    const float *Qw     = (const float *)d_in[7];
    const float *Qb     = (const float *)d_in[8];
    const float *Ow     = (const float *)d_in[9];
    const float *Obias  = (const float *)d_in[10];
    const float *OutW   = (const float *)d_in[11];
    const float *OutB   = (const float *)d_in[12];
    float *out = (float *)d_out;

    float *emb, *E, *Hall, *OutAll;
    cudaGetSymbolAddress((void **)&emb,    g_emb);
    cudaGetSymbolAddress((void **)&E,      g_E);
    cudaGetSymbolAddress((void **)&Hall,   g_Hall);
    cudaGetSymbolAddress((void **)&OutAll, g_OutAll);

    // 1) conv embedding for all 8192 images
    conv_embed_kernel<<<NIMG, 256>>>(In, conv1w, conv1b, conv2w, conv2b, emb);
    // 2) E = emb @ Qw[:750] + Qb   (no activation)
    gemm100_kernel<false><<<NIMG / 64, 256>>>(emb, Qw, Qb, E, NIMG, EMB);
    // 3) sequential recurrence (parallel over batch), stores all H_t
    recurrence_kernel<<<BB, 512>>>(Rw, Rb, Qw, E, Hall);
    // 4) OutAll = tanh(Hall @ O_w + O_b)
    gemm100_kernel<true><<<NIMG / 64, 256>>>(Hall, Ow, Obias, OutAll, NIMG, HSZ);
    // 5) logits + softmax
    logits_kernel<<<BB, 256>>>(OutAll, OutW, OutB, out);
}